// round 5
// baseline (speedup 1.0000x reference)
#include <cuda_runtime.h>
#include <cuda_bf16.h>
#include <cstdint>

// Problem constants
#define NN 8
#define AA 256
#define HH 128
#define WW 128
#define CC 19
#define CP1 20
#define HT 1024
#define WT 1024
#define RPB 8              // h-rows per stats block
#define ACOLS 64           // a-columns per stats block

// Device scratch (no cudaMalloc allowed)
__device__ float gSums[CP1 * AA];
__device__ float gSq[CP1 * AA];
__device__ float gCount[32];
__device__ float gS[CP1 * CC];
__device__ unsigned char gLab[NN * HH * WW];
__device__ unsigned short gLW[NN * HH * WW];   // per-row sorted (label<<8 | w)
__device__ int gIs64;

// ---------------------------------------------------------------------------
// K0: zero accumulators + detect target dtype (int32 vs int64).
// int64 labels in [0,19): every odd 32-bit word is a zero high-word.
// ---------------------------------------------------------------------------
__global__ void zero_detect_kernel(const int* __restrict__ tw) {
    __shared__ int anynz;
    int i = blockIdx.x * 256 + threadIdx.x;
    if (i < CP1 * AA) { gSums[i] = 0.f; gSq[i] = 0.f; }
    if (i < 32) gCount[i] = 0.f;

    if (blockIdx.x == 0) {
        if (threadIdx.x == 0) anynz = 0;
        __syncthreads();
        int v = 0;
        #pragma unroll
        for (int k = 0; k < 16; k++) {
            int idx = threadIdx.x * 16 + k;          // 0..4095
            v |= tw[idx * 2 + 1];                    // word idx <= 8191 (safe)
        }
        if (v != 0) atomicOr(&anynz, 1);
        __syncthreads();
        if (threadIdx.x == 0) gIs64 = (anynz == 0) ? 1 : 0;
    }
}

// ---------------------------------------------------------------------------
// K0b: per-row label fetch + counting sort. One block per (n,h) row.
// Writes gLW (sorted packed label|w, ushort), gLab (raw bytes), gCount.
// ---------------------------------------------------------------------------
__global__ void sort_kernel(const int* __restrict__ tw) {
    __shared__ int cnt[CP1];
    __shared__ int offs[CP1];
    const int t = threadIdx.x;          // 0..127 (w)
    const int row = blockIdx.x;         // n*HH + h
    const int n = row >> 7;
    const int h = row & 127;

    long long eidx = ((long long)n * HT + (long long)h * 8) * WT + (long long)t * 8;
    int raw = gIs64 ? tw[eidx * 2] : tw[eidx];
    int l0 = (raw == 255) ? 0 : raw;
    if (l0 < 0) l0 = 0;
    if (l0 > CP1 - 1) l0 = CP1 - 1;

    if (t < CP1) cnt[t] = 0;
    __syncthreads();
    atomicAdd(&cnt[l0], 1);
    gLab[(size_t)row * WW + t] = (unsigned char)(raw & 0xFF);
    __syncthreads();
    if (t == 0) {
        int run = 0;
        #pragma unroll
        for (int c = 0; c < CP1; c++) { offs[c] = run; run += cnt[c]; }
    }
    if (t < CP1) atomicAdd(&gCount[t], (float)cnt[t]);
    __syncthreads();
    int pos = atomicAdd(&offs[l0], 1);
    gLW[(size_t)row * WW + pos] = (unsigned short)((l0 << 8) | t);
}

// ---------------------------------------------------------------------------
// K1: stats. Block = (a-quarter of 64, h-block of 8 rows, n). 256 threads,
// 76KB smem -> 3 CTA/SM. Per row: 32 floats/thread staged GMEM->regs->smem
// (conflict-free), with the next row's 32 LDGs issued BEFORE the accumulation
// phase so DRAM latency overlaps the smem-bound accum. Accum: 4 groups of 2
// warps each walk 32 pre-sorted pixels with running register accumulators,
// flushing to private smem bins on class change. One atomic flush per block.
// ---------------------------------------------------------------------------
__global__ __launch_bounds__(256, 3)
void stats_kernel(const float* __restrict__ features) {
    __shared__ float buf[ACOLS * 129];               // 33024 B
    __shared__ float accS[4 * CP1 * ACOLS];          // 20480 B
    __shared__ float accQ[4 * CP1 * ACOLS];          // 20480 B
    __shared__ unsigned short lwsm[RPB * 128];       // 2048 B

    const int t   = threadIdx.x;        // 0..255
    const int g   = t >> 6;             // pixel group 0..3
    const int tl  = t & 63;             // owned a-column within quarter
    const int w32 = t & 31;             // staging lane (w)
    const int rg  = t >> 5;             // staging row group 0..7
    const int q   = blockIdx.x;         // a-quarter 0..3
    const int hb  = blockIdx.y;         // 0..15
    const int n   = blockIdx.z;
    const int aBase = q * ACOLS;

    // zero accumulators + preload sorted lw for the 8 rows
    #pragma unroll
    for (int i = t; i < 4 * CP1 * ACOLS; i += 256) { accS[i] = 0.f; accQ[i] = 0.f; }
    {
        const int lwbase = (n * HH + hb * RPB) * 128;
        #pragma unroll
        for (int i = t; i < RPB * 128; i += 256) lwsm[i] = gLW[lwbase + i];
    }

    const float* fbase = features + ((size_t)(n * AA + aBase)) * (HH * WW)
                       + (size_t)(hb * RPB) * WW;

    // prologue: load row 0 into registers (8 a-rows x 4 w-chunks per thread)
    float pf[32];
    #pragma unroll
    for (int k = 0; k < 8; k++)
        #pragma unroll
        for (int m = 0; m < 4; m++)
            pf[k * 4 + m] = fbase[(size_t)(rg + 8 * k) * (HH * WW) + w32 + 32 * m];

    #pragma unroll 1
    for (int ch = 0; ch < RPB; ch++) {
        __syncthreads();   // buf free (prev accum done); lwsm/acc ready on ch=0

        // store current row tile to smem (conflict-free)
        #pragma unroll
        for (int k = 0; k < 8; k++)
            #pragma unroll
            for (int m = 0; m < 4; m++)
                buf[(rg + 8 * k) * 129 + w32 + 32 * m] = pf[k * 4 + m];

        // issue next row's loads NOW; awaited at the next iteration's STS,
        // overlapping the accumulation phase below
        if (ch + 1 < RPB) {
            #pragma unroll
            for (int k = 0; k < 8; k++)
                #pragma unroll
                for (int m = 0; m < 4; m++)
                    pf[k * 4 + m] = fbase[(size_t)(rg + 8 * k) * (HH * WW)
                                          + (ch + 1) * WW + w32 + 32 * m];
        }
        __syncthreads();   // buf filled

        // sorted-run accumulation: group g -> sorted pixels [32g, 32g+32)
        {
            const unsigned short* lwr = lwsm + ch * 128 + g * 32;
            int run = lwr[0] >> 8;
            float s = 0.f, sq = 0.f;
            #pragma unroll 8
            for (int i = 0; i < 32; i++) {
                int lw = lwr[i];                  // uniform LDS (broadcast)
                int w  = lw & 255;
                int l  = lw >> 8;
                float f = buf[tl * 129 + w];      // conflict-free
                if (l != run) {                   // group-uniform branch, rare
                    accS[(g * CP1 + run) * ACOLS + tl] += s;
                    accQ[(g * CP1 + run) * ACOLS + tl] += sq;
                    s = 0.f; sq = 0.f; run = l;
                }
                s  += f;
                sq += f * f;
            }
            accS[(g * CP1 + run) * ACOLS + tl] += s;
            accQ[(g * CP1 + run) * ACOLS + tl] += sq;
        }
    }
    __syncthreads();

    // merge 4 groups, single coalesced atomic flush
    #pragma unroll
    for (int i = t; i < CP1 * ACOLS; i += 256) {
        int c = i >> 6, al = i & 63;
        float vs = 0.f, vq = 0.f;
        #pragma unroll
        for (int gg = 0; gg < 4; gg++) {
            vs += accS[(gg * CP1 + c) * ACOLS + al];
            vq += accQ[(gg * CP1 + c) * ACOLS + al];
        }
        atomicAdd(&gSums[c * AA + aBase + al], vs);
        atomicAdd(&gSq[c * AA + aBase + al],   vq);
    }
}

// ---------------------------------------------------------------------------
// K2: grid = 19 blocks (one per class l; ncov row 19 is never read since
// lab0 <= 18 always). Block l: ncov[l,a] in registers (a = threadIdx.x),
// then S[l,c] = ratio * sum_a ncov[l,a]*(W[c,a]-W[l,a])^2 for all c via
// warp-shuffle + smem reduction.
// ---------------------------------------------------------------------------
__global__ __launch_bounds__(256)
void cov_s_kernel(const float* __restrict__ fc,
                  const float* __restrict__ Ave,
                  const float* __restrict__ CoV,
                  const float* __restrict__ Amount,
                  const int* __restrict__ ratio_p) {
    __shared__ float red[CC][8];
    const int l = blockIdx.x;          // 0..18
    const int t = threadIdx.x;         // 0..255 == feature index a
    const int lane = t & 31, wid = t >> 5;

    float cntv = gCount[l];
    float cntc = (cntv == 0.f) ? 1.f : cntv;
    float ave  = gSums[l * AA + t] / cntc;
    float var  = gSq[l * AA + t] / cntc - ave * ave;
    float denom = cntv + Amount[l];
    float wcv  = (denom > 0.f) ? (cntv / denom) : 0.f;
    float dd   = Ave[l * AA + t] - ave;
    float ncov = CoV[l * AA + t] * (1.f - wcv) + var * wcv
               + wcv * (1.f - wcv) * dd * dd;
    float wl = fc[l * AA + t];
    float r  = (float)(*ratio_p);      // low 4 LE bytes: correct for i32 & i64

    #pragma unroll 1
    for (int c = 0; c < CC; c++) {
        float d = fc[c * AA + t] - wl;
        float v = ncov * d * d;
        #pragma unroll
        for (int o = 16; o; o >>= 1) v += __shfl_down_sync(0xffffffffu, v, o);
        if (lane == 0) red[c][wid] = v;
    }
    __syncthreads();
    if (t < CC) {
        float s = 0.f;
        #pragma unroll
        for (int k = 0; k < 8; k++) s += red[t][k];
        gS[l * CC + t] = r * s;
    }
}

// ---------------------------------------------------------------------------
// K3: out[n,c,h,w] = y[n,c,h,w] + 0.5 * S[l(n,h,w), c] * (l != 255)
// 4 blocks per (n,c) -> 608 blocks, 256 threads, float4/uchar4
// ---------------------------------------------------------------------------
__global__ __launch_bounds__(256, 4)
void aug_kernel(const float* __restrict__ y, float* __restrict__ out) {
    __shared__ float Ssm[CP1];
    const int t = threadIdx.x;                 // 0..255
    const int bq = blockIdx.x & 3;             // h-quarter
    const int nc = blockIdx.x >> 2;
    const int n = nc / CC;
    const int c = nc % CC;

    if (t < CP1) Ssm[t] = (t < CC) ? (0.5f * gS[t * CC + c]) : 0.f;
    __syncthreads();

    const size_t plane = ((size_t)n * CC + c) * (HH * WW);
    const int qoff = bq * (HH * WW / 16);      // in float4 units
    const float4* y4 = (const float4*)(y + plane) + qoff;
    float4*       o4 = (float4*)(out + plane) + qoff;
    const uchar4* l4 = (const uchar4*)(gLab + (size_t)n * (HH * WW)) + qoff;

    #pragma unroll 4
    for (int i = t; i < (HH * WW) / 16; i += 256) {
        uchar4 lb = l4[i];
        float4 v  = y4[i];
        if (lb.x != 255) v.x += Ssm[lb.x];
        if (lb.y != 255) v.y += Ssm[lb.y];
        if (lb.z != 255) v.z += Ssm[lb.z];
        if (lb.w != 255) v.w += Ssm[lb.w];
        o4[i] = v;
    }
}

// ---------------------------------------------------------------------------
extern "C" void kernel_launch(void* const* d_in, const int* in_sizes, int n_in,
                              void* d_out, int out_size) {
    const float* features = (const float*)d_in[0];
    const float* y        = (const float*)d_in[1];
    const float* fc       = (const float*)d_in[2];
    const float* Ave      = (const float*)d_in[3];
    const float* CoV      = (const float*)d_in[4];
    const float* Amount   = (const float*)d_in[5];
    const int*   target_w = (const int*)d_in[6];   // int32 or int64 (probed)
    const int*   ratio    = (const int*)d_in[7];
    float*       out      = (float*)d_out;

    // K0: zero accumulators + dtype probe
    zero_detect_kernel<<<(CP1 * AA + 255) / 256, 256>>>(target_w);

    // K0b: per-row label sort
    sort_kernel<<<NN * HH, 128>>>(target_w);

    // K1: stats
    dim3 g1(4, HH / RPB, NN);
    stats_kernel<<<g1, 256>>>(features);

    // K2: covariance update + S table (parallel over classes)
    cov_s_kernel<<<CC, 256>>>(fc, Ave, CoV, Amount, ratio);

    // K3: output
    aug_kernel<<<NN * CC * 4, 256>>>(y, out);
}

// round 6
// speedup vs baseline: 1.0433x; 1.0433x over previous
#include <cuda_runtime.h>
#include <cuda_bf16.h>
#include <cstdint>

// Problem constants
#define NN 8
#define AA 256
#define HH 128
#define WW 128
#define CC 19
#define CP1 20
#define HT 1024
#define WT 1024
#define RPB 8              // h-rows per stats block
#define ACOLS 64           // a-columns per stats block

// Device scratch (no cudaMalloc allowed)
__device__ float gSums[CP1 * AA];
__device__ float gSq[CP1 * AA];
__device__ float gCount[32];
__device__ float gS[CP1 * CC];
__device__ unsigned char gLab[NN * HH * WW];
__device__ unsigned short gLW[NN * HH * WW];   // per-row sorted (label<<8 | w)
__device__ int gIs64;

// ---------------------------------------------------------------------------
// K0: zero accumulators + detect target dtype (int32 vs int64).
// int64 labels in [0,19): every odd 32-bit word is a zero high-word.
// ---------------------------------------------------------------------------
__global__ void zero_detect_kernel(const int* __restrict__ tw) {
    __shared__ int anynz;
    int i = blockIdx.x * 256 + threadIdx.x;
    if (i < CP1 * AA) { gSums[i] = 0.f; gSq[i] = 0.f; }
    if (i < 32) gCount[i] = 0.f;

    if (blockIdx.x == 0) {
        if (threadIdx.x == 0) anynz = 0;
        __syncthreads();
        int v = 0;
        #pragma unroll
        for (int k = 0; k < 16; k++) {
            int idx = threadIdx.x * 16 + k;          // 0..4095
            v |= tw[idx * 2 + 1];                    // word idx <= 8191 (safe)
        }
        if (v != 0) atomicOr(&anynz, 1);
        __syncthreads();
        if (threadIdx.x == 0) gIs64 = (anynz == 0) ? 1 : 0;
    }
}

// ---------------------------------------------------------------------------
// K0b: per-row label fetch + counting sort. One block per (n,h) row.
// Writes gLW (sorted packed label|w, ushort), gLab (raw bytes), gCount.
// ---------------------------------------------------------------------------
__global__ void sort_kernel(const int* __restrict__ tw) {
    __shared__ int cnt[CP1];
    __shared__ int offs[CP1];
    const int t = threadIdx.x;          // 0..127 (w)
    const int row = blockIdx.x;         // n*HH + h
    const int n = row >> 7;
    const int h = row & 127;

    long long eidx = ((long long)n * HT + (long long)h * 8) * WT + (long long)t * 8;
    int raw = gIs64 ? tw[eidx * 2] : tw[eidx];
    int l0 = (raw == 255) ? 0 : raw;
    if (l0 < 0) l0 = 0;
    if (l0 > CP1 - 1) l0 = CP1 - 1;

    if (t < CP1) cnt[t] = 0;
    __syncthreads();
    atomicAdd(&cnt[l0], 1);
    gLab[(size_t)row * WW + t] = (unsigned char)(raw & 0xFF);
    __syncthreads();
    if (t == 0) {
        int run = 0;
        #pragma unroll
        for (int c = 0; c < CP1; c++) { offs[c] = run; run += cnt[c]; }
    }
    if (t < CP1) atomicAdd(&gCount[t], (float)cnt[t]);
    __syncthreads();
    int pos = atomicAdd(&offs[l0], 1);
    gLW[(size_t)row * WW + pos] = (unsigned short)((l0 << 8) | t);
}

// ---------------------------------------------------------------------------
// K1: stats. Block = (a-quarter of 64, h-block of 8 rows, n). 256 threads.
// launch_bounds(256, 2): 128-reg budget so the pf[32] prefetch array STAYS IN
// REGISTERS (at occ 3 / 84 regs it spilled to local -> 3x traffic).
// Per row: 32 floats/thread staged GMEM->regs->smem (conflict-free stride 129),
// next row's LDGs issued before the accumulation phase. Accum: 4 groups of 2
// warps walk 32 pre-sorted pixels with running register accumulators, flushing
// to private smem bins on class change. One atomic flush per block.
// ---------------------------------------------------------------------------
__global__ __launch_bounds__(256, 2)
void stats_kernel(const float* __restrict__ features) {
    __shared__ float buf[ACOLS * 129];               // 33024 B
    __shared__ float accS[4 * CP1 * ACOLS];          // 20480 B
    __shared__ float accQ[4 * CP1 * ACOLS];          // 20480 B
    __shared__ unsigned short lwsm[RPB * 128];       // 2048 B

    const int t   = threadIdx.x;        // 0..255
    const int g   = t >> 6;             // pixel group 0..3
    const int tl  = t & 63;             // owned a-column within quarter
    const int w32 = t & 31;             // staging lane (w)
    const int rg  = t >> 5;             // staging row group 0..7
    const int q   = blockIdx.x;         // a-quarter 0..3
    const int hb  = blockIdx.y;         // 0..15
    const int n   = blockIdx.z;
    const int aBase = q * ACOLS;

    // zero accumulators + preload sorted lw for the 8 rows
    #pragma unroll
    for (int i = t; i < 4 * CP1 * ACOLS; i += 256) { accS[i] = 0.f; accQ[i] = 0.f; }
    {
        const int lwbase = (n * HH + hb * RPB) * 128;
        #pragma unroll
        for (int i = t; i < RPB * 128; i += 256) lwsm[i] = gLW[lwbase + i];
    }

    const float* fbase = features + ((size_t)(n * AA + aBase)) * (HH * WW)
                       + (size_t)(hb * RPB) * WW;

    // prologue: load row 0 into registers (8 a-rows x 4 w-chunks per thread)
    float pf[32];
    #pragma unroll
    for (int k = 0; k < 8; k++)
        #pragma unroll
        for (int m = 0; m < 4; m++)
            pf[k * 4 + m] = fbase[(size_t)(rg + 8 * k) * (HH * WW) + w32 + 32 * m];

    #pragma unroll 1
    for (int ch = 0; ch < RPB; ch++) {
        __syncthreads();   // buf free (prev accum done); lwsm/acc ready on ch=0

        // store current row tile to smem (conflict-free)
        #pragma unroll
        for (int k = 0; k < 8; k++)
            #pragma unroll
            for (int m = 0; m < 4; m++)
                buf[(rg + 8 * k) * 129 + w32 + 32 * m] = pf[k * 4 + m];

        // issue next row's loads NOW; awaited at the next iteration's STS,
        // overlapping the accumulation phase below
        if (ch + 1 < RPB) {
            #pragma unroll
            for (int k = 0; k < 8; k++)
                #pragma unroll
                for (int m = 0; m < 4; m++)
                    pf[k * 4 + m] = fbase[(size_t)(rg + 8 * k) * (HH * WW)
                                          + (ch + 1) * WW + w32 + 32 * m];
        }
        __syncthreads();   // buf filled

        // sorted-run accumulation: group g -> sorted pixels [32g, 32g+32)
        {
            const unsigned short* lwr = lwsm + ch * 128 + g * 32;
            int run = lwr[0] >> 8;
            float s = 0.f, sq = 0.f;
            #pragma unroll 8
            for (int i = 0; i < 32; i++) {
                int lw = lwr[i];                  // uniform LDS (broadcast)
                int w  = lw & 255;
                int l  = lw >> 8;
                float f = buf[tl * 129 + w];      // conflict-free
                if (l != run) {                   // group-uniform branch, rare
                    accS[(g * CP1 + run) * ACOLS + tl] += s;
                    accQ[(g * CP1 + run) * ACOLS + tl] += sq;
                    s = 0.f; sq = 0.f; run = l;
                }
                s  += f;
                sq += f * f;
            }
            accS[(g * CP1 + run) * ACOLS + tl] += s;
            accQ[(g * CP1 + run) * ACOLS + tl] += sq;
        }
    }
    __syncthreads();

    // merge 4 groups, single coalesced atomic flush
    #pragma unroll
    for (int i = t; i < CP1 * ACOLS; i += 256) {
        int c = i >> 6, al = i & 63;
        float vs = 0.f, vq = 0.f;
        #pragma unroll
        for (int gg = 0; gg < 4; gg++) {
            vs += accS[(gg * CP1 + c) * ACOLS + al];
            vq += accQ[(gg * CP1 + c) * ACOLS + al];
        }
        atomicAdd(&gSums[c * AA + aBase + al], vs);
        atomicAdd(&gSq[c * AA + aBase + al],   vq);
    }
}

// ---------------------------------------------------------------------------
// K2: grid = 19 blocks (one per class l; ncov row 19 never read: lab0<=18).
// fc staged in smem (coalesced, high MLP); c-loop fully unrolled so the 19
// shuffle-reduction chains are independent and pipeline.
// ---------------------------------------------------------------------------
__global__ __launch_bounds__(256)
void cov_s_kernel(const float* __restrict__ fc,
                  const float* __restrict__ Ave,
                  const float* __restrict__ CoV,
                  const float* __restrict__ Amount,
                  const int* __restrict__ ratio_p) {
    __shared__ float Wsm[CC * AA];     // 19456 B
    __shared__ float red[CC][8];
    const int l = blockIdx.x;          // 0..18
    const int t = threadIdx.x;         // 0..255 == feature index a
    const int lane = t & 31, wid = t >> 5;

    // stage all of fc cooperatively (19 coalesced rows, batched LDGs)
    #pragma unroll
    for (int c = 0; c < CC; c++) Wsm[c * AA + t] = fc[c * AA + t];

    // independent loads for the ncov row (issued alongside the staging)
    float cntv = gCount[l];
    float sums = gSums[l * AA + t];
    float sq   = gSq[l * AA + t];
    float avev = Ave[l * AA + t];
    float covv = CoV[l * AA + t];
    float amov = Amount[l];
    float r    = (float)(*ratio_p);    // low 4 LE bytes: correct for i32 & i64

    float cntc = (cntv == 0.f) ? 1.f : cntv;
    float ave  = sums / cntc;
    float var  = sq / cntc - ave * ave;
    float denom = cntv + amov;
    float wcv  = (denom > 0.f) ? (cntv / denom) : 0.f;
    float dd   = avev - ave;
    float ncov = covv * (1.f - wcv) + var * wcv + wcv * (1.f - wcv) * dd * dd;

    __syncthreads();
    float wl = Wsm[l * AA + t];

    #pragma unroll
    for (int c = 0; c < CC; c++) {
        float d = Wsm[c * AA + t] - wl;
        float v = ncov * d * d;
        #pragma unroll
        for (int o = 16; o; o >>= 1) v += __shfl_down_sync(0xffffffffu, v, o);
        if (lane == 0) red[c][wid] = v;
    }
    __syncthreads();
    if (t < CC) {
        float s = 0.f;
        #pragma unroll
        for (int k = 0; k < 8; k++) s += red[t][k];
        gS[l * CC + t] = r * s;
    }
}

// ---------------------------------------------------------------------------
// K3: out[n,c,h,w] = y[n,c,h,w] + 0.5 * S[l(n,h,w), c] * (l != 255)
// 4 blocks per (n,c) -> 608 blocks, 256 threads, float4/uchar4
// ---------------------------------------------------------------------------
__global__ __launch_bounds__(256, 4)
void aug_kernel(const float* __restrict__ y, float* __restrict__ out) {
    __shared__ float Ssm[CP1];
    const int t = threadIdx.x;                 // 0..255
    const int bq = blockIdx.x & 3;             // h-quarter
    const int nc = blockIdx.x >> 2;
    const int n = nc / CC;
    const int c = nc % CC;

    if (t < CP1) Ssm[t] = (t < CC) ? (0.5f * gS[t * CC + c]) : 0.f;
    __syncthreads();

    const size_t plane = ((size_t)n * CC + c) * (HH * WW);
    const int qoff = bq * (HH * WW / 16);      // in float4 units
    const float4* y4 = (const float4*)(y + plane) + qoff;
    float4*       o4 = (float4*)(out + plane) + qoff;
    const uchar4* l4 = (const uchar4*)(gLab + (size_t)n * (HH * WW)) + qoff;

    #pragma unroll 4
    for (int i = t; i < (HH * WW) / 16; i += 256) {
        uchar4 lb = l4[i];
        float4 v  = y4[i];
        if (lb.x != 255) v.x += Ssm[lb.x];
        if (lb.y != 255) v.y += Ssm[lb.y];
        if (lb.z != 255) v.z += Ssm[lb.z];
        if (lb.w != 255) v.w += Ssm[lb.w];
        o4[i] = v;
    }
}

// ---------------------------------------------------------------------------
extern "C" void kernel_launch(void* const* d_in, const int* in_sizes, int n_in,
                              void* d_out, int out_size) {
    const float* features = (const float*)d_in[0];
    const float* y        = (const float*)d_in[1];
    const float* fc       = (const float*)d_in[2];
    const float* Ave      = (const float*)d_in[3];
    const float* CoV      = (const float*)d_in[4];
    const float* Amount   = (const float*)d_in[5];
    const int*   target_w = (const int*)d_in[6];   // int32 or int64 (probed)
    const int*   ratio    = (const int*)d_in[7];
    float*       out      = (float*)d_out;

    // K0: zero accumulators + dtype probe
    zero_detect_kernel<<<(CP1 * AA + 255) / 256, 256>>>(target_w);

    // K0b: per-row label sort
    sort_kernel<<<NN * HH, 128>>>(target_w);

    // K1: stats
    dim3 g1(4, HH / RPB, NN);
    stats_kernel<<<g1, 256>>>(features);

    // K2: covariance update + S table (parallel over classes)
    cov_s_kernel<<<CC, 256>>>(fc, Ave, CoV, Amount, ratio);

    // K3: output
    aug_kernel<<<NN * CC * 4, 256>>>(y, out);
}